// round 1
// baseline (speedup 1.0000x reference)
#include <cuda_runtime.h>
#include <cuda_bf16.h>
#include <math.h>

#define SEQ   2048
#define BATCH 128
#define FEAT  256
#define NPOS  1024          // single_eval_pos (fixed by problem setup)
#define NM1   (NPOS - 1)

// ---------------- scratch (device globals; no allocation allowed) -------------
__device__ float d_mean[BATCH * FEAT];
__device__ float d_rstd[BATCH * FEAT];
__device__ int   d_count[BATCH * FEAT];
__device__ int   d_order[BATCH * FEAT];
__device__ int   d_counts[BATCH];

// ---------------- Phase 1: per-(b,f) mean / 1/(std+eps), zero counters -------
// One block per batch, 1024 threads: thread (q,f) handles seq-quarter q of
// feature f. Coalesced 1 KB rows per iteration.
__global__ void stats_kernel(const float* __restrict__ x) {
    int b = blockIdx.x;
    int f = threadIdx.x & 255;
    int q = threadIdx.x >> 8;           // 0..3

    float sum = 0.f, sq = 0.f;
    const float* p = x + (size_t)(q * 256) * BATCH * FEAT + (size_t)b * FEAT + f;
#pragma unroll 8
    for (int s = 0; s < 256; s++) {
        float v = p[(size_t)s * BATCH * FEAT];
        sum += v;
        sq  += v * v;
    }

    __shared__ float ssum[4][256];
    __shared__ float ssq [4][256];
    ssum[q][f] = sum;
    ssq [q][f] = sq;
    __syncthreads();

    if (q == 0) {
        sum = ssum[0][f] + ssum[1][f] + ssum[2][f] + ssum[3][f];
        sq  = ssq [0][f] + ssq [1][f] + ssq [2][f] + ssq [3][f];
        float mean = sum * (1.0f / NPOS);
        float var  = fmaxf((sq - sum * mean) * (1.0f / NM1), 0.0f);
        float rstd = 1.0f / (sqrtf(var) + 1e-6f);
        d_mean[b * FEAT + f] = mean;
        d_rstd[b * FEAT + f] = rstd;
        d_count[b * FEAT + f] = 0;      // must re-zero on every graph replay
    }
}

// ---------------- Phase 2: per-batch SYRK + threshold counting ---------------
// grid (10 upper-tri tile pairs, BATCH), 256 threads, 64x64 tiles, BK=32.
// Each thread owns a 4x4 accumulator block. Normalization+clip applied on load.
#define TB 64
#define BK 32

__global__ void cov_kernel(const float* __restrict__ x) {
    int b = blockIdx.y;

    // decode upper-triangular tile pair index -> (ti, tj), ti <= tj
    int p = blockIdx.x, ti = 0;
    while (p >= 4 - ti) { p -= 4 - ti; ti++; }
    int tj = ti + p;
    int i0 = ti * TB, j0 = tj * TB;

    __shared__ float Ai[BK][TB + 4];
    __shared__ float Aj[BK][TB + 4];
    __shared__ float mi[TB], ri[TB], mj[TB], rj[TB];

    int tid = threadIdx.x;
    if (tid < TB) {
        mi[tid] = d_mean[b * FEAT + i0 + tid];
        ri[tid] = d_rstd[b * FEAT + i0 + tid];
        mj[tid] = d_mean[b * FEAT + j0 + tid];
        rj[tid] = d_rstd[b * FEAT + j0 + tid];
    }

    float acc[4][4] = {};
    int tx = tid & 15, ty = tid >> 4;

    for (int k0 = 0; k0 < NPOS; k0 += BK) {
        __syncthreads();
#pragma unroll
        for (int t = 0; t < 8; t++) {
            int e  = tid + t * 256;          // 0..2047
            int kk = e >> 6, c = e & 63;
            size_t g = (size_t)(k0 + kk) * BATCH * FEAT + (size_t)b * FEAT;
            float vi = x[g + i0 + c];
            float vj = x[g + j0 + c];
            Ai[kk][c] = fminf(fmaxf((vi - mi[c]) * ri[c], -100.f), 100.f);
            Aj[kk][c] = fminf(fmaxf((vj - mj[c]) * rj[c], -100.f), 100.f);
        }
        __syncthreads();

#pragma unroll
        for (int kk = 0; kk < BK; kk++) {
            float4 a = *(const float4*)&Ai[kk][ty * 4];
            float4 c4 = *(const float4*)&Aj[kk][tx * 4];
            acc[0][0] += a.x * c4.x; acc[0][1] += a.x * c4.y;
            acc[0][2] += a.x * c4.z; acc[0][3] += a.x * c4.w;
            acc[1][0] += a.y * c4.x; acc[1][1] += a.y * c4.y;
            acc[1][2] += a.y * c4.z; acc[1][3] += a.y * c4.w;
            acc[2][0] += a.z * c4.x; acc[2][1] += a.z * c4.y;
            acc[2][2] += a.z * c4.z; acc[2][3] += a.z * c4.w;
            acc[3][0] += a.w * c4.x; acc[3][1] += a.w * c4.y;
            acc[3][2] += a.w * c4.z; acc[3][3] += a.w * c4.w;
        }
    }

    // cov[i][j] = acc/(n-1) > 0.999  <=>  acc > 0.999*(n-1)
    const float thr = 0.999f * (float)NM1;
#pragma unroll
    for (int ii = 0; ii < 4; ii++) {
#pragma unroll
        for (int jj = 0; jj < 4; jj++) {
            int gi = i0 + ty * 4 + ii;
            int gj = j0 + tx * 4 + jj;
            if (gi <= gj && acc[ii][jj] > thr)
                atomicAdd(&d_count[b * FEAT + gj], 1);  // rare except diagonal
        }
    }
}

// ---------------- Phase 3: stable partition -> order + counts ----------------
__global__ void select_kernel() {
    int b = blockIdx.x;
    __shared__ int sel[FEAT];
    sel[threadIdx.x] = (d_count[b * FEAT + threadIdx.x] == 1) ? 1 : 0;
    __syncthreads();
    if (threadIdx.x == 0) {
        int c = 0;
        for (int f = 0; f < FEAT; f++) if (sel[f])  d_order[b * FEAT + c++] = f;
        d_counts[b] = c;
        for (int f = 0; f < FEAT; f++) if (!sel[f]) d_order[b * FEAT + c++] = f;
    }
}

// ---------------- Phase 4: gather + mask over full SEQ ----------------------
#define ROWS_PER_BLOCK 8
__global__ void gather_kernel(const float* __restrict__ x, float* __restrict__ out) {
    int blk = blockIdx.x;
    int b   = blk % BATCH;
    int s0  = (blk / BATCH) * ROWS_PER_BLOCK;
    int k   = threadIdx.x;

    int src  = d_order[b * FEAT + k];
    bool keep = k < d_counts[b];
    size_t base = (size_t)b * FEAT;

#pragma unroll
    for (int r = 0; r < ROWS_PER_BLOCK; r++) {
        size_t off = (size_t)(s0 + r) * BATCH * FEAT + base;
        out[off + k] = keep ? x[off + src] : 0.0f;
    }
}

// ---------------- launch -----------------------------------------------------
extern "C" void kernel_launch(void* const* d_in, const int* in_sizes, int n_in,
                              void* d_out, int out_size) {
    const float* x = (const float*)d_in[0];
    float* out = (float*)d_out;
    (void)in_sizes; (void)n_in; (void)out_size;

    stats_kernel <<<BATCH, 1024>>>(x);
    cov_kernel   <<<dim3(10, BATCH), 256>>>(x);
    select_kernel<<<BATCH, FEAT>>>();
    gather_kernel<<<(SEQ / ROWS_PER_BLOCK) * BATCH, FEAT>>>(x, out);
}

// round 3
// speedup vs baseline: 1.6609x; 1.6609x over previous
#include <cuda_runtime.h>
#include <cuda_bf16.h>
#include <math.h>
#include <stdint.h>

#define SEQ   2048
#define BATCH 128
#define FEAT  256
#define NPOS  1024
#define NM1   1023
#define BF    (BATCH * FEAT)       // row stride in elements (32768)

// ---------------- scratch (device globals; no allocation allowed) ------------
__device__ float d_mean[BF];
__device__ float d_rstd[BF];
__device__ int   d_count[BF];
__device__ int   d_order[BF];
__device__ int   d_counts[BATCH];

// ---------------- Phase 1: per-(b,f) mean / 1/(std+eps), zero counters -------
__global__ void stats_kernel(const float* __restrict__ x) {
    int b = blockIdx.x;
    int f = threadIdx.x & 255;
    int q = threadIdx.x >> 8;           // 0..3

    float sum = 0.f, sq = 0.f;
    const float* p = x + (size_t)(q * 256) * BF + (size_t)b * FEAT + f;
#pragma unroll 8
    for (int s = 0; s < 256; s++) {
        float v = p[(size_t)s * BF];
        sum += v;
        sq  += v * v;
    }

    __shared__ float ssum[4][256];
    __shared__ float ssq [4][256];
    ssum[q][f] = sum;
    ssq [q][f] = sq;
    __syncthreads();

    if (q == 0) {
        sum = ssum[0][f] + ssum[1][f] + ssum[2][f] + ssum[3][f];
        sq  = ssq [0][f] + ssq [1][f] + ssq [2][f] + ssq [3][f];
        float mean = sum * (1.0f / NPOS);
        float var  = fmaxf((sq - sum * mean) * (1.0f / NM1), 0.0f);
        float rstd = 1.0f / (sqrtf(var) + 1e-6f);
        d_mean[b * FEAT + f] = mean;
        d_rstd[b * FEAT + f] = rstd;
        d_count[b * FEAT + f] = 0;      // re-zero on every graph replay
    }
}

// ---------------- Phase 2: tf32 tensor-core SYRK + threshold counting --------
// grid (2, BATCH): CTA mb covers output rows [mb*128, mb*128+128) x all 256 cols.
// 512 threads = 16 warps in 4x4 grid; warp tile 32x64; thread holds 2x8x4 accums.
// Mainloop computes raw G = X^T X (tf32 mma); epilogue forms
//   cov*(n-1) = r_i r_j (G - n m_i m_j) and counts entries > 0.999*(n-1).
#define BK     16
#define NCHUNK (NPOS / BK)

__device__ __forceinline__ uint32_t f2tf32(float v) {
    uint32_t r; asm("cvt.rna.tf32.f32 %0, %1;" : "=r"(r) : "f"(v)); return r;
}
// XOR-8 swizzle: conflict-free for float4 transpose stores AND mma frag loads.
__device__ __forceinline__ int swz(int k, int f) {
    return k * FEAT + (f ^ ((k & 7) << 3));
}

__global__ void __launch_bounds__(512, 1) cov_kernel(const float* __restrict__ x) {
    __shared__ uint32_t sbuf[2][BK * FEAT];   // 2 x 16 KB

    int b    = blockIdx.y;
    int mb   = blockIdx.x;                    // 0 or 1
    int tid  = threadIdx.x;
    int lane = tid & 31;
    int w    = tid >> 5;                      // 0..15
    int wm   = w & 3, wn = w >> 2;            // 4x4 warp grid
    int gid  = lane >> 2, tig = lane & 3;     // mma thread mapping

    const float* xb = x + (size_t)b * FEAT;

    // loader mapping: thread owns two (k, float4) slots, f fixed across chunks
    int f4    = tid & 63;
    int kA    = tid >> 6;                     // 0..7
    int kB    = kA + 8;                       // 8..15
    int fbase = f4 * 4;

    float acc[2][8][4];
#pragma unroll
    for (int m = 0; m < 2; m++)
#pragma unroll
        for (int n = 0; n < 8; n++)
#pragma unroll
            for (int c = 0; c < 4; c++) acc[m][n][c] = 0.f;

    // prefetch chunk 0
    float4 rA = *(const float4*)(xb + (size_t)kA * BF + fbase);
    float4 rB = *(const float4*)(xb + (size_t)kB * BF + fbase);

    // store chunk 0
    {
        uint4 ua = make_uint4(f2tf32(rA.x), f2tf32(rA.y), f2tf32(rA.z), f2tf32(rA.w));
        uint4 ub = make_uint4(f2tf32(rB.x), f2tf32(rB.y), f2tf32(rB.z), f2tf32(rB.w));
        *(uint4*)&sbuf[0][swz(kA, fbase)] = ua;
        *(uint4*)&sbuf[0][swz(kB, fbase)] = ub;
    }
    __syncthreads();

    int amBase = mb * 128 + wm * 32;          // + mt*16 + gid (+8)
    int bnBase = wn * 64;                     // + nt*8  + gid

    for (int c = 0; c < NCHUNK; c++) {
        int buf = c & 1;
        if (c + 1 < NCHUNK) {
            size_t off = (size_t)((c + 1) * BK) * BF;
            rA = *(const float4*)(xb + off + (size_t)kA * BF + fbase);
            rB = *(const float4*)(xb + off + (size_t)kB * BF + fbase);
        }
        const uint32_t* sb = sbuf[buf];

#pragma unroll
        for (int ks = 0; ks < 2; ks++) {
            int k0 = ks * 8 + tig;
            uint32_t af[2][4];
#pragma unroll
            for (int mt = 0; mt < 2; mt++) {
                int fm = amBase + mt * 16 + gid;
                af[mt][0] = sb[swz(k0,     fm)];
                af[mt][1] = sb[swz(k0,     fm + 8)];
                af[mt][2] = sb[swz(k0 + 4, fm)];
                af[mt][3] = sb[swz(k0 + 4, fm + 8)];
            }
#pragma unroll
            for (int nt = 0; nt < 8; nt++) {
                int fn = bnBase + nt * 8 + gid;
                uint32_t b0 = sb[swz(k0,     fn)];
                uint32_t b1 = sb[swz(k0 + 4, fn)];
#pragma unroll
                for (int mt = 0; mt < 2; mt++) {
                    asm volatile(
                        "mma.sync.aligned.m16n8k8.row.col.f32.tf32.tf32.f32 "
                        "{%0,%1,%2,%3},{%4,%5,%6,%7},{%8,%9},{%0,%1,%2,%3};"
                        : "+f"(acc[mt][nt][0]), "+f"(acc[mt][nt][1]),
                          "+f"(acc[mt][nt][2]), "+f"(acc[mt][nt][3])
                        : "r"(af[mt][0]), "r"(af[mt][1]), "r"(af[mt][2]), "r"(af[mt][3]),
                          "r"(b0), "r"(b1));
                }
            }
        }

        if (c + 1 < NCHUNK) {
            // writes buf^1, whose last readers finished before the sync that
            // ended iteration c-1 -> one sync per iteration suffices.
            int nb = (c + 1) & 1;
            uint4 ua = make_uint4(f2tf32(rA.x), f2tf32(rA.y), f2tf32(rA.z), f2tf32(rA.w));
            uint4 ub = make_uint4(f2tf32(rB.x), f2tf32(rB.y), f2tf32(rB.z), f2tf32(rB.w));
            *(uint4*)&sbuf[nb][swz(kA, fbase)] = ua;
            *(uint4*)&sbuf[nb][swz(kB, fbase)] = ub;
        }
        __syncthreads();
    }

    // epilogue: cov*(n-1) = (G - n*mi*mj) * ri * rj ; count per ROW (gi<=gj)
    const float thr = 0.999f * (float)NM1;
#pragma unroll
    for (int mt = 0; mt < 2; mt++) {
#pragma unroll
        for (int rr = 0; rr < 2; rr++) {
            int gi = amBase + mt * 16 + gid + rr * 8;
            float mi = __ldg(&d_mean[b * FEAT + gi]);
            float ri = __ldg(&d_rstd[b * FEAT + gi]);
#pragma unroll
            for (int nt = 0; nt < 8; nt++) {
#pragma unroll
                for (int cc = 0; cc < 2; cc++) {
                    int gj = bnBase + nt * 8 + tig * 2 + cc;
                    float mj = __ldg(&d_mean[b * FEAT + gj]);
                    float rj = __ldg(&d_rstd[b * FEAT + gj]);
                    float v  = (acc[mt][nt][rr * 2 + cc] - 1024.0f * mi * mj) * ri * rj;
                    if (gi <= gj && v > thr)
                        atomicAdd(&d_count[b * FEAT + gi], 1);   // rare except diag
                }
            }
        }
    }
}

// ---------------- Phase 3: stable partition -> order + counts ----------------
__global__ void select_kernel() {
    int b = blockIdx.x;
    __shared__ int sel[FEAT];
    sel[threadIdx.x] = (d_count[b * FEAT + threadIdx.x] == 1) ? 1 : 0;
    __syncthreads();
    if (threadIdx.x == 0) {
        int c = 0;
        for (int f = 0; f < FEAT; f++) if (sel[f])  d_order[b * FEAT + c++] = f;
        d_counts[b] = c;
        for (int f = 0; f < FEAT; f++) if (!sel[f]) d_order[b * FEAT + c++] = f;
    }
}

// ---------------- Phase 4: gather + mask over full SEQ ----------------------
// Fast path: counts==FEAT implies sel is all-true -> order is identity and
// keep mask is all-ones -> pure vectorized copy.
#define ROWS_PER_BLOCK 8
__global__ void gather_kernel(const float* __restrict__ x, float* __restrict__ out) {
    int blk = blockIdx.x;
    int b   = blk % BATCH;
    int s0  = (blk / BATCH) * ROWS_PER_BLOCK;
    int tid = threadIdx.x;

    if (d_counts[b] == FEAT) {
        const float4* src = (const float4*)(x   + (size_t)s0 * BF + (size_t)b * FEAT);
        float4*       dst = (float4*)      (out + (size_t)s0 * BF + (size_t)b * FEAT);
#pragma unroll
        for (int i = 0; i < 2; i++) {
            int idx = tid + i * 256;            // 0..511 over 8 rows x 64 f4
            int r = idx >> 6, f = idx & 63;
            dst[(size_t)r * (BF / 4) + f] = src[(size_t)r * (BF / 4) + f];
        }
        return;
    }

    int  src  = d_order[b * FEAT + tid];
    bool keep = tid < d_counts[b];
    size_t base = (size_t)b * FEAT;
#pragma unroll
    for (int r = 0; r < ROWS_PER_BLOCK; r++) {
        size_t off = (size_t)(s0 + r) * BF + base;
        out[off + tid] = keep ? x[off + src] : 0.0f;
    }
}

// ---------------- launch -----------------------------------------------------
extern "C" void kernel_launch(void* const* d_in, const int* in_sizes, int n_in,
                              void* d_out, int out_size) {
    const float* x = (const float*)d_in[0];
    float* out = (float*)d_out;
    (void)in_sizes; (void)n_in; (void)out_size;

    stats_kernel <<<BATCH, 1024>>>(x);
    cov_kernel   <<<dim3(2, BATCH), 512>>>(x);
    select_kernel<<<BATCH, FEAT>>>();
    gather_kernel<<<(SEQ / ROWS_PER_BLOCK) * BATCH, FEAT>>>(x, out);
}